// round 2
// baseline (speedup 1.0000x reference)
#include <cuda_runtime.h>

#define NN 50000
#define NE 1600000
#define NG 64
#define FN 32
#define FE 16
#define HD 64
#define NL 3
#define BN_EPS 1e-5f

// ---------------- static device scratch (no allocs allowed) ----------------
__device__ float g_h[(size_t)NN * HD];          // current node features
__device__ float g_z[(size_t)NN * HD];          // h + agg
__device__ float g_z2[(size_t)NN * HD];         // MLP output (pre-BN)
__device__ float g_e[(size_t)NE * HD];          // edge embeddings, CSR-permuted
__device__ int   g_src[NE];                     // src node per CSR slot
__device__ int   g_rowptr[NN + 1];
__device__ int   g_cnt[NN];                     // histogram, then cursor
__device__ float g_part[148 * 128];             // BN partial sums
__device__ float g_mu[HD], g_inv[HD];
__device__ float g_gsum[NG * HD];
__device__ float g_gcnt[NG];
__device__ int   g_is64;                        // index dtype flag

// read index i from a buffer that is either int64 or int32
__device__ __forceinline__ int load_idx(const void* p, long long i, int is64) {
    if (is64) return (int)((const long long*)p)[i];
    return ((const int*)p)[i];
}

// Detect whether ei is int64 (all odd int32 slots == 0) or int32.
__global__ void probe_k(const int* __restrict__ ei32) {
    if (threadIdx.x != 0 || blockIdx.x != 0) return;
    int all0 = 1;
    for (int k = 0; k < 256; k++) {
        long long slot = 1 + 2LL * ((long long)k * 6247);  // odd slots < 2*NE
        if (slot < 2LL * NE && ei32[slot] != 0) { all0 = 0; break; }
    }
    g_is64 = all0;
}

// ---------------- helpers ----------------
__global__ void zero_cnt_k() {
    int i = blockIdx.x * blockDim.x + threadIdx.x;
    if (i < NN) g_cnt[i] = 0;
}

__global__ void zero_pool_k() {
    int i = blockIdx.x * blockDim.x + threadIdx.x;
    if (i < NG * HD) g_gsum[i] = 0.f;
    if (i < NG) g_gcnt[i] = 0.f;
}

// h = x @ node_W + node_b   (warp per row, lane owns 2 cols)
__global__ void node_embed_k(const float* __restrict__ x,
                             const float* __restrict__ W,
                             const float* __restrict__ b) {
    int r = (blockIdx.x * blockDim.x + threadIdx.x) >> 5;
    int lane = threadIdx.x & 31;
    if (r >= NN) return;
    float2 acc = make_float2(b[2 * lane], b[2 * lane + 1]);
    const float* xr = x + (size_t)r * FN;
#pragma unroll
    for (int k = 0; k < FN; k++) {
        float xv = __ldg(xr + k);
        float2 wv = *(const float2*)(W + k * HD + 2 * lane);
        acc.x += xv * wv.x;
        acc.y += xv * wv.y;
    }
    *(float2*)(g_h + (size_t)r * HD + 2 * lane) = acc;
}

__global__ void hist_k(const void* __restrict__ ei) {
    int is64 = g_is64;
    for (long long i = blockIdx.x * blockDim.x + threadIdx.x; i < NE;
         i += (long long)gridDim.x * blockDim.x)
        atomicAdd(&g_cnt[load_idx(ei, NE + i, is64)], 1);
}

// single-block exclusive scan of g_cnt -> g_rowptr; also seeds cursor (g_cnt)
__global__ void scan_k() {
    __shared__ int sd[1024];
    __shared__ int srun;
    int tid = threadIdx.x;
    if (tid == 0) srun = 0;
    __syncthreads();
    for (int base = 0; base < NN; base += 1024) {
        int i = base + tid;
        int v = (i < NN) ? g_cnt[i] : 0;
        sd[tid] = v;
        __syncthreads();
#pragma unroll
        for (int off = 1; off < 1024; off <<= 1) {
            int t = (tid >= off) ? sd[tid - off] : 0;
            __syncthreads();
            sd[tid] += t;
            __syncthreads();
        }
        int excl = srun + sd[tid] - v;
        if (i < NN) { g_rowptr[i] = excl; g_cnt[i] = excl; }
        __syncthreads();
        if (tid == 1023) srun += sd[1023];
        __syncthreads();
    }
    if (tid == 0) g_rowptr[NN] = srun;
}

// compute e = edge_attr @ edge_W + edge_b, written into CSR slot; record src
__global__ void edge_build_k(const void* __restrict__ ei,
                             const float* __restrict__ ea,
                             const float* __restrict__ W,
                             const float* __restrict__ b) {
    long long e = (long long)(blockIdx.x * blockDim.x + threadIdx.x) >> 5;
    int lane = threadIdx.x & 31;
    if (e >= NE) return;
    int pos = 0;
    if (lane == 0) {
        int is64 = g_is64;
        int dst = load_idx(ei, NE + e, is64);
        pos = atomicAdd(&g_cnt[dst], 1);
        g_src[pos] = load_idx(ei, e, is64);
    }
    pos = __shfl_sync(0xffffffffu, pos, 0);
    float2 acc = make_float2(b[2 * lane], b[2 * lane + 1]);
    const float* er = ea + (size_t)e * FE;
#pragma unroll
    for (int k = 0; k < FE; k++) {
        float v = __ldg(er + k);
        float2 wv = *(const float2*)(W + k * HD + 2 * lane);
        acc.x += v * wv.x;
        acc.y += v * wv.y;
    }
    *(float2*)(g_e + (size_t)pos * HD + 2 * lane) = acc;
}

// warp per dst node: z = h + sum_in relu(h[src] + e)
__global__ void agg_z_k() {
    int v = (blockIdx.x * blockDim.x + threadIdx.x) >> 5;
    int lane = threadIdx.x & 31;
    if (v >= NN) return;
    int s0 = g_rowptr[v], s1 = g_rowptr[v + 1];
    float2 acc = make_float2(0.f, 0.f);
    int srcNext = (s0 < s1) ? g_src[s0] : 0;
    for (int s = s0; s < s1; s++) {
        int sc = srcNext;
        if (s + 1 < s1) srcNext = g_src[s + 1];
        float2 ev = *(const float2*)(g_e + (size_t)s * HD + 2 * lane);
        float2 hs = *(const float2*)(g_h + (size_t)sc * HD + 2 * lane);
        acc.x += fmaxf(hs.x + ev.x, 0.f);
        acc.y += fmaxf(hs.y + ev.y, 0.f);
    }
    float2 hv = *(const float2*)(g_h + (size_t)v * HD + 2 * lane);
    *(float2*)(g_z + (size_t)v * HD + 2 * lane) =
        make_float2(hv.x + acc.x, hv.y + acc.y);
}

// z2 = relu(z @ W1 + b1) @ W2 + b2    (warp per row)
__global__ __launch_bounds__(256) void mlp_k(const float* __restrict__ W1,
                                             const float* __restrict__ b1,
                                             const float* __restrict__ W2,
                                             const float* __restrict__ b2) {
    __shared__ __align__(16) float sW1[HD * 2 * HD];  // 64x128
    __shared__ float sb1[128];
    __shared__ float sb2[64];
    __shared__ __align__(16) float zb[8][64];
    __shared__ __align__(16) float hb[8][128];
    int tid = threadIdx.x;
    for (int i = tid; i < HD * 2 * HD; i += 256) sW1[i] = W1[i];
    if (tid < 128) sb1[tid] = b1[tid];
    if (tid < 64) sb2[tid] = b2[tid];
    __syncthreads();
    int w = tid >> 5, lane = tid & 31;
    int r = blockIdx.x * 8 + w;
    if (r >= NN) return;
    zb[w][lane] = g_z[(size_t)r * HD + lane];
    zb[w][lane + 32] = g_z[(size_t)r * HD + lane + 32];
    __syncwarp();
    // hidden: lane owns 4 consecutive cols
    float4 acc = *(const float4*)&sb1[4 * lane];
#pragma unroll
    for (int k = 0; k < 64; k++) {
        float zk = zb[w][k];
        float4 wv = *(const float4*)&sW1[k * 128 + 4 * lane];
        acc.x += zk * wv.x;
        acc.y += zk * wv.y;
        acc.z += zk * wv.z;
        acc.w += zk * wv.w;
    }
    acc.x = fmaxf(acc.x, 0.f);
    acc.y = fmaxf(acc.y, 0.f);
    acc.z = fmaxf(acc.z, 0.f);
    acc.w = fmaxf(acc.w, 0.f);
    *(float4*)&hb[w][4 * lane] = acc;
    __syncwarp();
    float2 o = make_float2(sb2[2 * lane], sb2[2 * lane + 1]);
#pragma unroll
    for (int m = 0; m < 128; m += 4) {
        float4 hh = *(const float4*)&hb[w][m];
        float2 w0 = *(const float2*)(W2 + (size_t)m * 64 + 2 * lane);
        float2 w1v = *(const float2*)(W2 + (size_t)(m + 1) * 64 + 2 * lane);
        float2 w2v = *(const float2*)(W2 + (size_t)(m + 2) * 64 + 2 * lane);
        float2 w3v = *(const float2*)(W2 + (size_t)(m + 3) * 64 + 2 * lane);
        o.x += hh.x * w0.x + hh.y * w1v.x + hh.z * w2v.x + hh.w * w3v.x;
        o.y += hh.x * w0.y + hh.y * w1v.y + hh.z * w2v.y + hh.w * w3v.y;
    }
    *(float2*)(g_z2 + (size_t)r * HD + 2 * lane) = o;
}

// BN partial sums: grid must be 148
__global__ void bn_stats_k() {
    int c = threadIdx.x & 63, rg = threadIdx.x >> 6;
    float s = 0.f, s2 = 0.f;
    for (int r = blockIdx.x * 4 + rg; r < NN; r += 148 * 4) {
        float v = g_z2[(size_t)r * HD + c];
        s += v;
        s2 += v * v;
    }
    __shared__ float ps[256], ps2[256];
    ps[threadIdx.x] = s;
    ps2[threadIdx.x] = s2;
    __syncthreads();
    if (threadIdx.x < 128) {
        ps[threadIdx.x] += ps[threadIdx.x + 128];
        ps2[threadIdx.x] += ps2[threadIdx.x + 128];
    }
    __syncthreads();
    if (threadIdx.x < 64) {
        g_part[blockIdx.x * 128 + threadIdx.x] = ps[threadIdx.x] + ps[threadIdx.x + 64];
        g_part[blockIdx.x * 128 + 64 + threadIdx.x] = ps2[threadIdx.x] + ps2[threadIdx.x + 64];
    }
}

__global__ void bn_finalize_k() {
    int t = threadIdx.x;  // 64 threads
    float s = 0.f, s2 = 0.f;
    for (int i = 0; i < 148; i++) {
        s += g_part[i * 128 + t];
        s2 += g_part[i * 128 + 64 + t];
    }
    float mu = s / (float)NN;
    float var = s2 / (float)NN - mu * mu;
    g_mu[t] = mu;
    g_inv[t] = rsqrtf(var + BN_EPS);
}

__global__ void bn_apply_k(const float* __restrict__ gamma,
                           const float* __restrict__ beta) {
    int i = blockIdx.x * blockDim.x + threadIdx.x;
    if (i >= NN * HD) return;
    int c = i & 63;
    float v = g_z2[i];
    v = gamma[c] * (v - g_mu[c]) * g_inv[c] + beta[c];
    g_h[i] = fmaxf(v, 0.f);
}

__global__ void pool_k(const void* __restrict__ batch) {
    int i = blockIdx.x * blockDim.x + threadIdx.x;
    if (i >= NN * HD) return;
    int r = i >> 6, c = i & 63;
    int b = load_idx(batch, r, g_is64);
    atomicAdd(&g_gsum[b * HD + c], g_h[i]);
    if (c == 0) atomicAdd(&g_gcnt[b], 1.0f);
}

__global__ void final_k(const float* __restrict__ lw,
                        const float* __restrict__ lb,
                        float* __restrict__ out) {
    int g = (blockIdx.x * blockDim.x + threadIdx.x) >> 5;
    int lane = threadIdx.x & 31;
    if (g >= NG) return;
    float cnt = fmaxf(g_gcnt[g], 1.0f);
    float t = g_gsum[g * HD + lane] * lw[lane] +
              g_gsum[g * HD + lane + 32] * lw[lane + 32];
    t /= cnt;
#pragma unroll
    for (int off = 16; off; off >>= 1) t += __shfl_down_sync(0xffffffffu, t, off);
    if (lane == 0) out[g] = t + lb[0];
}

// ---------------- launcher ----------------
extern "C" void kernel_launch(void* const* d_in, const int* in_sizes, int n_in,
                              void* d_out, int out_size) {
    const float* x = (const float*)d_in[0];
    const float* ea = (const float*)d_in[1];
    const void* ei = d_in[2];
    const void* batch = d_in[3];
    const float* node_W = (const float*)d_in[4];
    const float* node_b = (const float*)d_in[5];
    const float* edge_W = (const float*)d_in[6];
    const float* edge_b = (const float*)d_in[7];
    const float* W1s = (const float*)d_in[8];
    const float* b1s = (const float*)d_in[9];
    const float* W2s = (const float*)d_in[10];
    const float* b2s = (const float*)d_in[11];
    const float* gammas = (const float*)d_in[12];
    const float* betas = (const float*)d_in[13];
    const float* lin_W = (const float*)d_in[14];
    const float* lin_b = (const float*)d_in[15];
    float* out = (float*)d_out;

    probe_k<<<1, 32>>>((const int*)ei);
    zero_cnt_k<<<(NN + 255) / 256, 256>>>();
    node_embed_k<<<(NN * 32 + 255) / 256, 256>>>(x, node_W, node_b);
    hist_k<<<2048, 256>>>(ei);
    scan_k<<<1, 1024>>>();
    edge_build_k<<<((size_t)NE * 32 + 255) / 256, 256>>>(ei, ea, edge_W, edge_b);

    for (int l = 0; l < NL; l++) {
        agg_z_k<<<(NN * 32 + 255) / 256, 256>>>();
        mlp_k<<<(NN + 7) / 8, 256>>>(W1s + (size_t)l * 64 * 128,
                                     b1s + (size_t)l * 128,
                                     W2s + (size_t)l * 128 * 64,
                                     b2s + (size_t)l * 64);
        bn_stats_k<<<148, 256>>>();
        bn_finalize_k<<<1, 64>>>();
        bn_apply_k<<<(NN * HD + 255) / 256, 256>>>(gammas + l * 64, betas + l * 64);
    }

    zero_pool_k<<<(NG * HD + 255) / 256, 256>>>();
    pool_k<<<(NN * HD + 255) / 256, 256>>>(batch);
    final_k<<<(NG * 32 + 255) / 256, 256>>>(lin_W, lin_b, out);
}

// round 4
// speedup vs baseline: 1.1531x; 1.1531x over previous
#include <cuda_runtime.h>
#include <cuda_fp16.h>

#define NN 50000
#define NE 1600000
#define NG 64
#define FN 32
#define FE 16
#define HD 64
#define NL 3
#define BN_EPS 1e-5f
#define SCAN_B 1024
#define SCAN_NB ((NN + SCAN_B - 1) / SCAN_B)   // 49

// ---------------- static device scratch (no allocs allowed) ----------------
__device__ float  g_h[(size_t)NN * HD];         // current node features
__device__ float  g_z[(size_t)NN * HD];         // h + agg
__device__ float  g_z2[(size_t)NN * HD];        // MLP output (pre-BN)
__device__ __half g_e[(size_t)NE * HD];         // edge embeddings (fp16), CSR-permuted
__device__ int    g_src[NE];                    // src node per CSR slot
__device__ int    g_rowptr[NN + 1];
__device__ int    g_cnt[NN];                    // histogram, then cursor
__device__ int    g_bsum[SCAN_NB];
__device__ int    g_boff[SCAN_NB];
__device__ float  g_part[148 * 128];            // BN partial sums
__device__ float  g_mu[HD], g_inv[HD];
__device__ int    g_is64;                       // index dtype flag

__device__ __forceinline__ int load_idx(const void* p, long long i, int is64) {
    if (is64) return (int)((const long long*)p)[i];
    return ((const int*)p)[i];
}

// Detect whether ei is int64 (all odd int32 slots == 0) or int32.
__global__ void probe_k(const int* __restrict__ ei32) {
    if (threadIdx.x != 0 || blockIdx.x != 0) return;
    int all0 = 1;
    for (int k = 0; k < 256; k++) {
        long long slot = 1 + 2LL * ((long long)k * 6247);
        if (slot < 2LL * NE && ei32[slot] != 0) { all0 = 0; break; }
    }
    g_is64 = all0;
}

__global__ void zero_cnt_k() {
    int i = blockIdx.x * blockDim.x + threadIdx.x;
    if (i < NN) g_cnt[i] = 0;
}

// h = x @ node_W + node_b   (warp per row, lane owns 2 cols)
__global__ void node_embed_k(const float* __restrict__ x,
                             const float* __restrict__ W,
                             const float* __restrict__ b) {
    int r = (blockIdx.x * blockDim.x + threadIdx.x) >> 5;
    int lane = threadIdx.x & 31;
    if (r >= NN) return;
    float2 acc = make_float2(b[2 * lane], b[2 * lane + 1]);
    const float* xr = x + (size_t)r * FN;
#pragma unroll
    for (int k = 0; k < FN; k++) {
        float xv = __ldg(xr + k);
        float2 wv = *(const float2*)(W + k * HD + 2 * lane);
        acc.x += xv * wv.x;
        acc.y += xv * wv.y;
    }
    *(float2*)(g_h + (size_t)r * HD + 2 * lane) = acc;
}

__global__ void hist_k(const void* __restrict__ ei) {
    int is64 = g_is64;
    for (long long i = blockIdx.x * blockDim.x + threadIdx.x; i < NE;
         i += (long long)gridDim.x * blockDim.x)
        atomicAdd(&g_cnt[load_idx(ei, NE + i, is64)], 1);
}

// ---- 3-kernel coalesced exclusive scan of g_cnt -> g_rowptr (+cursor) ----
__global__ void scan_partial_k() {
    int i = blockIdx.x * SCAN_B + threadIdx.x;
    int v = (i < NN) ? g_cnt[i] : 0;
    int lane = threadIdx.x & 31, w = threadIdx.x >> 5;
#pragma unroll
    for (int off = 16; off; off >>= 1) v += __shfl_down_sync(0xffffffffu, v, off);
    __shared__ int ws[32];
    if (lane == 0) ws[w] = v;
    __syncthreads();
    if (w == 0) {
        int t = ws[lane];
#pragma unroll
        for (int off = 16; off; off >>= 1) t += __shfl_down_sync(0xffffffffu, t, off);
        if (lane == 0) g_bsum[blockIdx.x] = t;
    }
}

__global__ void scan_tops_k() {
    if (threadIdx.x != 0) return;
    int run = 0;
    for (int b = 0; b < SCAN_NB; b++) {
        g_boff[b] = run;
        run += g_bsum[b];
    }
    g_rowptr[NN] = run;
}

__global__ void scan_final_k() {
    int i = blockIdx.x * SCAN_B + threadIdx.x;
    int v = (i < NN) ? g_cnt[i] : 0;
    int lane = threadIdx.x & 31, w = threadIdx.x >> 5;
    int inc = v;
#pragma unroll
    for (int off = 1; off < 32; off <<= 1) {
        int n = __shfl_up_sync(0xffffffffu, inc, off);
        if (lane >= off) inc += n;
    }
    __shared__ int ws[32];
    if (lane == 31) ws[w] = inc;
    __syncthreads();
    if (w == 0) {
        int t = ws[lane];
        int e = t;
#pragma unroll
        for (int off = 1; off < 32; off <<= 1) {
            int n = __shfl_up_sync(0xffffffffu, e, off);
            if (lane >= off) e += n;
        }
        ws[lane] = e - t;  // exclusive warp offset
    }
    __syncthreads();
    int excl = g_boff[blockIdx.x] + ws[w] + inc - v;
    if (i < NN) { g_rowptr[i] = excl; g_cnt[i] = excl; }
}

// e = edge_attr @ edge_W + edge_b (fp16), written into CSR slot; record src
__global__ void edge_build_k(const void* __restrict__ ei,
                             const float* __restrict__ ea,
                             const float* __restrict__ W,
                             const float* __restrict__ b) {
    long long e = (long long)(blockIdx.x * blockDim.x + threadIdx.x) >> 5;
    int lane = threadIdx.x & 31;
    if (e >= NE) return;
    int pos = 0;
    if (lane == 0) {
        int is64 = g_is64;
        int dst = load_idx(ei, NE + e, is64);
        pos = atomicAdd(&g_cnt[dst], 1);
        g_src[pos] = load_idx(ei, e, is64);
    }
    pos = __shfl_sync(0xffffffffu, pos, 0);
    float2 acc = make_float2(b[2 * lane], b[2 * lane + 1]);
    const float* er = ea + (size_t)e * FE;
#pragma unroll
    for (int k = 0; k < FE; k++) {
        float v = __ldg(er + k);
        float2 wv = *(const float2*)(W + k * HD + 2 * lane);
        acc.x += v * wv.x;
        acc.y += v * wv.y;
    }
    ((__half2*)g_e)[(size_t)pos * 32 + lane] = __float22half2_rn(acc);
}

// warp per dst node: z = h + sum_in relu(h[src] + e)
__global__ void agg_z_k() {
    int v = (blockIdx.x * blockDim.x + threadIdx.x) >> 5;
    int lane = threadIdx.x & 31;
    if (v >= NN) return;
    int s0 = g_rowptr[v], s1 = g_rowptr[v + 1];
    float2 acc = make_float2(0.f, 0.f);
    const __half2* ep = (const __half2*)g_e;
    int srcNext = (s0 < s1) ? g_src[s0] : 0;
    for (int s = s0; s < s1; s++) {
        int sc = srcNext;
        if (s + 1 < s1) srcNext = g_src[s + 1];
        float2 ev = __half22float2(ep[(size_t)s * 32 + lane]);
        float2 hs = *(const float2*)(g_h + (size_t)sc * HD + 2 * lane);
        acc.x += fmaxf(hs.x + ev.x, 0.f);
        acc.y += fmaxf(hs.y + ev.y, 0.f);
    }
    float2 hv = *(const float2*)(g_h + (size_t)v * HD + 2 * lane);
    *(float2*)(g_z + (size_t)v * HD + 2 * lane) =
        make_float2(hv.x + acc.x, hv.y + acc.y);
}

// z2 = relu(z @ W1 + b1) @ W2 + b2    (warp per row, 16 rows/block)
__global__ __launch_bounds__(512) void mlp_k(const float* __restrict__ W1,
                                             const float* __restrict__ b1,
                                             const float* __restrict__ W2,
                                             const float* __restrict__ b2) {
    __shared__ __align__(16) float sW1[HD * 2 * HD];  // 64x128 = 32KB
    __shared__ float sb1[128];
    __shared__ float sb2[64];
    __shared__ __align__(16) float zb[16][64];
    __shared__ __align__(16) float hb[16][128];
    int tid = threadIdx.x;
    for (int i = tid; i < HD * 2 * HD; i += 512) sW1[i] = W1[i];
    if (tid < 128) sb1[tid] = b1[tid];
    else if (tid >= 128 && tid < 192) sb2[tid - 128] = b2[tid - 128];
    __syncthreads();
    int w = tid >> 5, lane = tid & 31;
    int r = blockIdx.x * 16 + w;
    if (r >= NN) return;
    zb[w][lane] = g_z[(size_t)r * HD + lane];
    zb[w][lane + 32] = g_z[(size_t)r * HD + lane + 32];
    __syncwarp();
    float4 acc = *(const float4*)&sb1[4 * lane];
#pragma unroll
    for (int k = 0; k < 64; k++) {
        float zk = zb[w][k];
        float4 wv = *(const float4*)&sW1[k * 128 + 4 * lane];
        acc.x += zk * wv.x;
        acc.y += zk * wv.y;
        acc.z += zk * wv.z;
        acc.w += zk * wv.w;
    }
    acc.x = fmaxf(acc.x, 0.f);
    acc.y = fmaxf(acc.y, 0.f);
    acc.z = fmaxf(acc.z, 0.f);
    acc.w = fmaxf(acc.w, 0.f);
    *(float4*)&hb[w][4 * lane] = acc;
    __syncwarp();
    float2 o = make_float2(sb2[2 * lane], sb2[2 * lane + 1]);
#pragma unroll
    for (int m = 0; m < 128; m += 4) {
        float4 hh = *(const float4*)&hb[w][m];
        float2 w0 = *(const float2*)(W2 + (size_t)m * 64 + 2 * lane);
        float2 w1v = *(const float2*)(W2 + (size_t)(m + 1) * 64 + 2 * lane);
        float2 w2v = *(const float2*)(W2 + (size_t)(m + 2) * 64 + 2 * lane);
        float2 w3v = *(const float2*)(W2 + (size_t)(m + 3) * 64 + 2 * lane);
        o.x += hh.x * w0.x + hh.y * w1v.x + hh.z * w2v.x + hh.w * w3v.x;
        o.y += hh.x * w0.y + hh.y * w1v.y + hh.z * w2v.y + hh.w * w3v.y;
    }
    *(float2*)(g_z2 + (size_t)r * HD + 2 * lane) = o;
}

// BN partial sums: grid must be 148
__global__ void bn_stats_k() {
    int c = threadIdx.x & 63, rg = threadIdx.x >> 6;
    float s = 0.f, s2 = 0.f;
    for (int r = blockIdx.x * 4 + rg; r < NN; r += 148 * 4) {
        float v = g_z2[(size_t)r * HD + c];
        s += v;
        s2 += v * v;
    }
    __shared__ float ps[256], ps2[256];
    ps[threadIdx.x] = s;
    ps2[threadIdx.x] = s2;
    __syncthreads();
    if (threadIdx.x < 128) {
        ps[threadIdx.x] += ps[threadIdx.x + 128];
        ps2[threadIdx.x] += ps2[threadIdx.x + 128];
    }
    __syncthreads();
    if (threadIdx.x < 64) {
        g_part[blockIdx.x * 128 + threadIdx.x] = ps[threadIdx.x] + ps[threadIdx.x + 64];
        g_part[blockIdx.x * 128 + 64 + threadIdx.x] = ps2[threadIdx.x] + ps2[threadIdx.x + 64];
    }
}

__global__ void bn_finalize_k() {
    int t = threadIdx.x;  // 64 threads
    float s = 0.f, s2 = 0.f;
    for (int i = 0; i < 148; i++) {
        s += g_part[i * 128 + t];
        s2 += g_part[i * 128 + 64 + t];
    }
    float mu = s / (float)NN;
    float var = s2 / (float)NN - mu * mu;
    g_mu[t] = mu;
    g_inv[t] = rsqrtf(var + BN_EPS);
}

__global__ void bn_apply_k(const float* __restrict__ gamma,
                           const float* __restrict__ beta) {
    int i = blockIdx.x * blockDim.x + threadIdx.x;
    if (i >= NN * HD) return;
    int c = i & 63;
    float v = g_z2[i];
    v = gamma[c] * (v - g_mu[c]) * g_inv[c] + beta[c];
    g_h[i] = fmaxf(v, 0.f);
}

// batch is sorted -> per-graph contiguous range. One block per graph;
// computes mean-pool and folds in the final linear head.
__global__ void pool_final_k(const void* __restrict__ batch,
                             const float* __restrict__ lw,
                             const float* __restrict__ lb,
                             float* __restrict__ out) {
    int g = blockIdx.x;
    int is64 = g_is64;
    __shared__ int s_range[2];
    if (threadIdx.x == 0) {
        int lo = 0, hi = NN;
        while (lo < hi) { int mid = (lo + hi) >> 1; if (load_idx(batch, mid, is64) < g) lo = mid + 1; else hi = mid; }
        s_range[0] = lo;
        hi = NN;
        while (lo < hi) { int mid = (lo + hi) >> 1; if (load_idx(batch, mid, is64) < g + 1) lo = mid + 1; else hi = mid; }
        s_range[1] = lo;
    }
    __syncthreads();
    int start = s_range[0], end = s_range[1];
    int c = threadIdx.x & 63, rg = threadIdx.x >> 6;  // 4 row groups
    float s = 0.f;
    for (int r = start + rg; r < end; r += 4) s += g_h[(size_t)r * HD + c];
    __shared__ float ps[256];
    ps[threadIdx.x] = s;
    __syncthreads();
    if (threadIdx.x < 128) ps[threadIdx.x] += ps[threadIdx.x + 128];
    __syncthreads();
    if (threadIdx.x < 64) {
        float gs = ps[threadIdx.x] + ps[threadIdx.x + 64];
        float cnt = fmaxf((float)(end - start), 1.0f);
        ps[threadIdx.x] = gs / cnt * lw[threadIdx.x];
    }
    __syncthreads();
    if (threadIdx.x < 32) {
        float t = ps[threadIdx.x] + ps[threadIdx.x + 32];
#pragma unroll
        for (int off = 16; off; off >>= 1) t += __shfl_down_sync(0xffffffffu, t, off);
        if (threadIdx.x == 0) out[g] = t + lb[0];
    }
}

// ---------------- launcher ----------------
extern "C" void kernel_launch(void* const* d_in, const int* in_sizes, int n_in,
                              void* d_out, int out_size) {
    const float* x = (const float*)d_in[0];
    const float* ea = (const float*)d_in[1];
    const void* ei = d_in[2];
    const void* batch = d_in[3];
    const float* node_W = (const float*)d_in[4];
    const float* node_b = (const float*)d_in[5];
    const float* edge_W = (const float*)d_in[6];
    const float* edge_b = (const float*)d_in[7];
    const float* W1s = (const float*)d_in[8];
    const float* b1s = (const float*)d_in[9];
    const float* W2s = (const float*)d_in[10];
    const float* b2s = (const float*)d_in[11];
    const float* gammas = (const float*)d_in[12];
    const float* betas = (const float*)d_in[13];
    const float* lin_W = (const float*)d_in[14];
    const float* lin_b = (const float*)d_in[15];
    float* out = (float*)d_out;

    probe_k<<<1, 32>>>((const int*)ei);
    zero_cnt_k<<<(NN + 255) / 256, 256>>>();
    node_embed_k<<<(NN * 32 + 255) / 256, 256>>>(x, node_W, node_b);
    hist_k<<<2048, 256>>>(ei);
    scan_partial_k<<<SCAN_NB, SCAN_B>>>();
    scan_tops_k<<<1, 32>>>();
    scan_final_k<<<SCAN_NB, SCAN_B>>>();
    edge_build_k<<<((size_t)NE * 32 + 255) / 256, 256>>>(ei, ea, edge_W, edge_b);

    for (int l = 0; l < NL; l++) {
        agg_z_k<<<(NN * 32 + 255) / 256, 256>>>();
        mlp_k<<<(NN + 15) / 16, 512>>>(W1s + (size_t)l * 64 * 128,
                                       b1s + (size_t)l * 128,
                                       W2s + (size_t)l * 128 * 64,
                                       b2s + (size_t)l * 64);
        bn_stats_k<<<148, 256>>>();
        bn_finalize_k<<<1, 64>>>();
        bn_apply_k<<<(NN * HD + 255) / 256, 256>>>(gammas + l * 64, betas + l * 64);
    }

    pool_final_k<<<NG, 256>>>(batch, lin_W, lin_b, out);
}